// round 1
// baseline (speedup 1.0000x reference)
#include <cuda_runtime.h>
#include <cstdint>

// Problem constants
#define B_    16
#define L_    4096
#define D_    512
#define D1_   256
#define DF_   64
#define H_    511            // (4096-16)/8 + 1
#define NROWS (B_*H_)        // 8176
#define M_    (B_*L_)        // 65536
#define EPS_  1e-8f

// Scratch (no allocations allowed)
__device__ float g_Y1[(size_t)M_*D1_];  // leaky(X@W1+b1)          : 67 MB
__device__ float g_Xe[(size_t)M_*DF_];  // encoded                  : 16.8 MB
__device__ float g_pp[NROWS*DF_];       // per-patch means          : 2 MB
__device__ float g_z [NROWS*DF_];       // per-patch aggregated     : 2 MB
__device__ float g_U [(size_t)M_*DF_];  // overlap-added            : 16.8 MB

// ---------------------------------------------------------------------------
// Register-tiled SGEMM: C[M,N] = act(A[M,K] @ B[K,N] + bias[N])
// 256 threads. BM/BN/BK tile, TM x TN microtile per thread.
// Assumes M%BM==0, N%BN==0, K%BK==0 (true for all our shapes).
// ---------------------------------------------------------------------------
template<int BM,int BN,int BK,int TM,int TN,bool ACT>
__global__ void __launch_bounds__(256)
gemm_bias(const float* __restrict__ A, const float* __restrict__ Bw,
          const float* __restrict__ bias, float* __restrict__ C,
          int M, int K, int N)
{
    __shared__ float As[BK][BM];   // transposed A tile
    __shared__ float Bs[BK][BN];

    const int tid = threadIdx.x;
    const int bx  = blockIdx.x;    // N tile
    const int by  = blockIdx.y;    // M tile

    const int tx = tid % (BN/TN);
    const int ty = tid / (BN/TN);

    float acc[TM][TN];
#pragma unroll
    for (int i=0;i<TM;i++)
#pragma unroll
        for (int j=0;j<TN;j++) acc[i][j] = 0.f;

    constexpr int A4 = BM*BK/4;
    constexpr int B4 = BK*BN/4;

    for (int k0 = 0; k0 < K; k0 += BK) {
        // load A tile (BM x BK), store transposed
#pragma unroll
        for (int idx = tid; idx < A4; idx += 256) {
            int row = idx / (BK/4);
            int c4  = idx % (BK/4);
            const float4 v = *(const float4*)&A[((size_t)(by*BM+row))*K + k0 + c4*4];
            As[c4*4+0][row] = v.x;
            As[c4*4+1][row] = v.y;
            As[c4*4+2][row] = v.z;
            As[c4*4+3][row] = v.w;
        }
        // load B tile (BK x BN)
#pragma unroll
        for (int idx = tid; idx < B4; idx += 256) {
            int row = idx / (BN/4);
            int c4  = idx % (BN/4);
            *(float4*)&Bs[row][c4*4] =
                *(const float4*)&Bw[((size_t)(k0+row))*N + bx*BN + c4*4];
        }
        __syncthreads();

#pragma unroll
        for (int kk = 0; kk < BK; kk++) {
            float a[TM], b[TN];
#pragma unroll
            for (int i=0;i<TM;i+=4) *(float4*)&a[i] = *(const float4*)&As[kk][ty*TM+i];
#pragma unroll
            for (int j=0;j<TN;j+=4) *(float4*)&b[j] = *(const float4*)&Bs[kk][tx*TN+j];
#pragma unroll
            for (int i=0;i<TM;i++)
#pragma unroll
                for (int j=0;j<TN;j++) acc[i][j] += a[i]*b[j];
        }
        __syncthreads();
    }

#pragma unroll
    for (int i=0;i<TM;i++) {
        const size_t row = (size_t)(by*BM + ty*TM + i);
#pragma unroll
        for (int j=0;j<TN;j++) {
            const int col = bx*BN + tx*TN + j;
            float v = acc[i][j] + bias[col];
            if (ACT) v = (v > 0.f) ? v : 0.01f*v;
            C[row*N + col] = v;
        }
    }
}

// ---------------------------------------------------------------------------
// Per-patch mean over PATCH=16 rows (stride 8)
// ---------------------------------------------------------------------------
__global__ void patch_mean_kernel(const float* __restrict__ Xe, float* __restrict__ pp)
{
    const int n = blockIdx.x;          // 0..NROWS-1
    const int f = threadIdx.x;         // 0..63
    const int b  = n / H_;
    const int hh = n % H_;
    const float* base = Xe + ((size_t)b*L_ + hh*8)*DF_ + f;
    float s = 0.f;
#pragma unroll
    for (int p = 0; p < 16; p++) s += base[p*DF_];
    pp[n*DF_ + f] = s * (1.f/16.f);
}

// ---------------------------------------------------------------------------
// Fused per-row attention:
//   q,k,v = pp@Wq/Wk/Wv ; qn,kn normalized
//   M[i,j] = qn_i kn_j - kn_i qn_j ; A = relu(tanh(M))
//   top-8 per row (ties -> lowest index; ties at 0 are value-irrelevant)
//   renormalize, Av_i = sum_j A_ij v_j ; z = leaky(Av@W_agg + b_agg)
// One block of 64 threads per row n.
// ---------------------------------------------------------------------------
__global__ void attn_kernel(const float* __restrict__ pp,
                            const float* __restrict__ Wq, const float* __restrict__ Wk,
                            const float* __restrict__ Wv,
                            const float* __restrict__ Wagg, const float* __restrict__ bagg,
                            float* __restrict__ z)
{
    const int n = blockIdx.x;
    const int i = threadIdx.x;   // 0..63
    __shared__ float sp[DF_], sq[DF_], sk[DF_], sv[DF_], sAv[DF_];

    sp[i] = pp[n*DF_ + i];
    __syncthreads();

    float q = 0.f, k = 0.f, v = 0.f;
#pragma unroll
    for (int j = 0; j < DF_; j++) {
        const float x = sp[j];
        q += x * Wq[j*DF_ + i];
        k += x * Wk[j*DF_ + i];
        v += x * Wv[j*DF_ + i];
    }
    sq[i] = q; sk[i] = k; sv[i] = v;
    __syncthreads();

    float nq = 0.f, nk = 0.f;
#pragma unroll
    for (int j = 0; j < DF_; j++) { nq += sq[j]*sq[j]; nk += sk[j]*sk[j]; }
    const float inv_nq = 1.f / (sqrtf(nq) + EPS_);
    const float inv_nk = 1.f / (sqrtf(nk) + EPS_);

    const float qi = sq[i]*inv_nq;
    const float ki = sk[i]*inv_nk;

    float a[DF_];
#pragma unroll
    for (int j = 0; j < DF_; j++) {
        const float m = qi*(sk[j]*inv_nk) - ki*(sq[j]*inv_nq);
        const float t = tanhf(m);
        a[j] = (t > 0.f) ? t : 0.f;
    }

    // top-8 selection, strict > gives lowest-index tie break (matches jax)
    float tmp[DF_];
#pragma unroll
    for (int j = 0; j < DF_; j++) tmp[j] = a[j];

    unsigned long long bits = 0ull;
    float sum8 = 0.f;
    for (int t = 0; t < 8; t++) {
        float best = -1.f; int bi = 0;
        for (int j = 0; j < DF_; j++)
            if (tmp[j] > best) { best = tmp[j]; bi = j; }
        tmp[bi] = -2.f;
        bits |= (1ull << bi);
        sum8 += best;
    }
    const float inv_den = 1.f / fmaxf(sum8, EPS_);

    float av = 0.f;
#pragma unroll
    for (int j = 0; j < DF_; j++)
        if ((bits >> j) & 1ull) av += a[j]*sv[j];
    av *= inv_den;

    sAv[i] = av;
    __syncthreads();

    float acc = bagg[i];
#pragma unroll
    for (int j = 0; j < DF_; j++) acc += sAv[j]*Wagg[j*DF_ + i];
    z[n*DF_ + i] = (acc > 0.f) ? acc : 0.01f*acc;
}

// ---------------------------------------------------------------------------
// Overlap-add + divide by coverage count (closed form; count is 1 or 2)
// U[b,l,f] = (1/cnt) * sum_{h covering l} z[b,h,f]
// ---------------------------------------------------------------------------
__global__ void overlap_kernel(const float* __restrict__ z, float* __restrict__ U)
{
    const int idx = blockIdx.x*blockDim.x + threadIdx.x;   // over M_*DF_
    const int f = idx % DF_;
    const int l = (idx / DF_) % L_;
    const int b = idx / (DF_*L_);

    int hlo = (l >= 15) ? (l - 15 + 7) / 8 : 0;   // ceil((l-15)/8) clamped to 0
    int hhi = l / 8; if (hhi > H_-1) hhi = H_-1;

    float s = 0.f;
    for (int hh = hlo; hh <= hhi; hh++)
        s += z[((size_t)b*H_ + hh)*DF_ + f];
    U[idx] = s / (float)(hhi - hlo + 1);
}

// ---------------------------------------------------------------------------
extern "C" void kernel_launch(void* const* d_in, const int* in_sizes, int n_in,
                              void* d_out, int out_size)
{
    const float* X    = (const float*)d_in[0];
    const float* W1   = (const float*)d_in[1];
    const float* b1   = (const float*)d_in[2];
    const float* W2   = (const float*)d_in[3];
    const float* b2   = (const float*)d_in[4];
    const float* Wq   = (const float*)d_in[5];
    const float* Wk   = (const float*)d_in[6];
    const float* Wv   = (const float*)d_in[7];
    const float* Wagg = (const float*)d_in[8];
    const float* bagg = (const float*)d_in[9];
    const float* Wdec = (const float*)d_in[10];
    const float* bdec = (const float*)d_in[11];
    float* out = (float*)d_out;

    float *Y1, *Xe, *pp, *z, *U;
    cudaGetSymbolAddress((void**)&Y1, g_Y1);
    cudaGetSymbolAddress((void**)&Xe, g_Xe);
    cudaGetSymbolAddress((void**)&pp, g_pp);
    cudaGetSymbolAddress((void**)&z,  g_z);
    cudaGetSymbolAddress((void**)&U,  g_U);

    // 1) Y1 = leaky(X @ W1 + b1)    [65536,512]x[512,256]
    gemm_bias<128,128,16,8,8,true>
        <<<dim3(D1_/128, M_/128), 256>>>(X, W1, b1, Y1, M_, D_, D1_);

    // 2) Xe = Y1 @ W2 + b2          [65536,256]x[256,64]
    gemm_bias<128,64,16,8,4,false>
        <<<dim3(1, M_/128), 256>>>(Y1, W2, b2, Xe, M_, D1_, DF_);

    // 3) per-patch means
    patch_mean_kernel<<<NROWS, 64>>>(Xe, pp);

    // 4) fused qkv + attention + top-8 + aggregate
    attn_kernel<<<NROWS, 64>>>(pp, Wq, Wk, Wv, Wagg, bagg, z);

    // 5) overlap-add with coverage normalization
    overlap_kernel<<<(M_*DF_)/256, 256>>>(z, U);

    // 6) out = U @ Wdec + bdec      [65536,64]x[64,512]
    gemm_bias<128,128,16,8,8,false>
        <<<dim3(D_/128, M_/128), 256>>>(U, Wdec, bdec, out, M_, DF_, D_);
}